// round 1
// baseline (speedup 1.0000x reference)
#include <cuda_runtime.h>

#define NN    6000
#define FIN   300
#define HIDD  128
#define NH    8
#define ALPHAK 0.2f
#define MAXNNZ 4000000
#define SCAN_CH 6   // ceil(6000/1024)

// ---------------- device scratch (static, no allocations) ----------------
__device__ float g_Wh[NH * NN * HIDD];       // 24.6 MB  [h][n][o]
__device__ float g_f1[NH * NN];
__device__ float g_f2[NH * NN];
__device__ float g_hcat[NN * NH * HIDD];     // 24.6 MB  [n][h*128+o]
__device__ float g_Wh2[NN * HIDD];           // 3 MB
__device__ float g_g1[NN];
__device__ float g_g2[NN];
__device__ int   g_rowptr[NN + 1];
__device__ int   g_cols[MAXNNZ];

// ---------------- CSR build ----------------
__global__ __launch_bounds__(128) void count_kernel(const float* __restrict__ adj) {
    int row  = blockIdx.x * 4 + (threadIdx.x >> 5);
    int lane = threadIdx.x & 31;
    if (row >= NN) return;
    const float4* arow = reinterpret_cast<const float4*>(adj + (size_t)row * NN);
    int cnt = 0;
    for (int v = lane; v < NN / 4; v += 32) {
        float4 a = arow[v];
        cnt += (a.x > 0.f) + (a.y > 0.f) + (a.z > 0.f) + (a.w > 0.f);
    }
    #pragma unroll
    for (int o = 16; o; o >>= 1) cnt += __shfl_down_sync(0xffffffffu, cnt, o);
    if (lane == 0) g_rowptr[row + 1] = cnt;
}

__global__ __launch_bounds__(1024) void scan_kernel() {
    __shared__ int part[1024];
    int t = threadIdx.x;
    int base = t * SCAN_CH;
    int loc[SCAN_CH];
    int s = 0;
    #pragma unroll
    for (int i = 0; i < SCAN_CH; i++) {
        int idx = base + i;
        int v = (idx < NN) ? g_rowptr[idx + 1] : 0;
        s += v;
        loc[i] = s;  // inclusive within thread
    }
    part[t] = s;
    __syncthreads();
    for (int off = 1; off < 1024; off <<= 1) {
        int v = 0;
        if (t >= off) v = part[t - off];
        __syncthreads();
        if (t >= off) part[t] += v;
        __syncthreads();
    }
    int excl = (t == 0) ? 0 : part[t - 1];
    #pragma unroll
    for (int i = 0; i < SCAN_CH; i++) {
        int idx = base + i;
        if (idx < NN) g_rowptr[idx + 1] = excl + loc[i];
    }
    if (t == 0) g_rowptr[0] = 0;
}

__global__ __launch_bounds__(128) void fill_kernel(const float* __restrict__ adj) {
    int row  = blockIdx.x * 4 + (threadIdx.x >> 5);
    int lane = threadIdx.x & 31;
    if (row >= NN) return;
    const float4* arow = reinterpret_cast<const float4*>(adj + (size_t)row * NN);
    int base = g_rowptr[row];
    for (int v0 = 0; v0 < NN / 4; v0 += 32) {
        int v = v0 + lane;
        int c = 0;
        unsigned bits = 0;
        if (v < NN / 4) {
            float4 a = arow[v];
            bits = (unsigned)(a.x > 0.f) | ((unsigned)(a.y > 0.f) << 1)
                 | ((unsigned)(a.z > 0.f) << 2) | ((unsigned)(a.w > 0.f) << 3);
            c = __popc(bits);
        }
        // warp inclusive scan of c
        int p = c;
        #pragma unroll
        for (int o = 1; o < 32; o <<= 1) {
            int q = __shfl_up_sync(0xffffffffu, p, o);
            if (lane >= o) p += q;
        }
        int excl = p - c;
        int tot  = __shfl_sync(0xffffffffu, p, 31);
        if (v < NN / 4) {
            int pos = base + excl;
            int col = v * 4;
            if (bits & 1u) g_cols[pos++] = col;
            if (bits & 2u) g_cols[pos++] = col + 1;
            if (bits & 4u) g_cols[pos++] = col + 2;
            if (bits & 8u) g_cols[pos++] = col + 3;
        }
        base += tot;
    }
}

// ---------------- SGEMM: C[64xM tile, 128] = A[M,K] @ B[K,128] ----------------
// cSel: 0 -> C = g_Wh (+batch stride), 1 -> C = g_Wh2. A==nullptr -> A = g_hcat.
template <int BK>
__global__ __launch_bounds__(128) void sgemm_k(const float* __restrict__ A,
                                               const float* __restrict__ B,
                                               int M, int K, int ldA,
                                               long strideB, int cSel) {
    __shared__ float As[BK][64];
    __shared__ float Bs[BK][128];
    const float* Ab = A ? A : g_hcat;
    const float* Bb = B + strideB * blockIdx.y;
    float* Cb = (cSel ? g_Wh2 : g_Wh) + (cSel ? 0L : (long)blockIdx.y * NN * HIDD);

    int tid = threadIdx.x;
    int tx = tid & 15;   // 0..15 -> 8 output cols each
    int ty = tid >> 4;   // 0..7  -> 8 output rows each
    int m0 = blockIdx.x * 64;

    float acc[8][8];
    #pragma unroll
    for (int i = 0; i < 8; i++)
        #pragma unroll
        for (int j = 0; j < 8; j++) acc[i][j] = 0.f;

    for (int k0 = 0; k0 < K; k0 += BK) {
        // load A tile (c = idx/64, r = idx%64): conflict-free STS
        #pragma unroll
        for (int idx = tid; idx < 64 * BK; idx += 128) {
            int c = idx >> 6, r = idx & 63;
            int gm = m0 + r;
            As[c][r] = (gm < M) ? Ab[(size_t)gm * ldA + k0 + c] : 0.f;
        }
        // load B tile: coalesced
        #pragma unroll
        for (int idx = tid; idx < BK * 128; idx += 128) {
            int r = idx >> 7, c = idx & 127;
            Bs[r][c] = Bb[(size_t)(k0 + r) * 128 + c];
        }
        __syncthreads();
        #pragma unroll
        for (int kk = 0; kk < BK; kk++) {
            float a[8], b[8];
            float4 a0 = *reinterpret_cast<const float4*>(&As[kk][ty * 8]);
            float4 a1 = *reinterpret_cast<const float4*>(&As[kk][ty * 8 + 4]);
            float4 b0 = *reinterpret_cast<const float4*>(&Bs[kk][tx * 8]);
            float4 b1 = *reinterpret_cast<const float4*>(&Bs[kk][tx * 8 + 4]);
            a[0]=a0.x; a[1]=a0.y; a[2]=a0.z; a[3]=a0.w;
            a[4]=a1.x; a[5]=a1.y; a[6]=a1.z; a[7]=a1.w;
            b[0]=b0.x; b[1]=b0.y; b[2]=b0.z; b[3]=b0.w;
            b[4]=b1.x; b[5]=b1.y; b[6]=b1.z; b[7]=b1.w;
            #pragma unroll
            for (int i = 0; i < 8; i++)
                #pragma unroll
                for (int j = 0; j < 8; j++)
                    acc[i][j] = fmaf(a[i], b[j], acc[i][j]);
        }
        __syncthreads();
    }
    #pragma unroll
    for (int i = 0; i < 8; i++) {
        int gm = m0 + ty * 8 + i;
        if (gm < M) {
            float4 o0 = make_float4(acc[i][0], acc[i][1], acc[i][2], acc[i][3]);
            float4 o1 = make_float4(acc[i][4], acc[i][5], acc[i][6], acc[i][7]);
            *reinterpret_cast<float4*>(&Cb[(size_t)gm * 128 + tx * 8])     = o0;
            *reinterpret_cast<float4*>(&Cb[(size_t)gm * 128 + tx * 8 + 4]) = o1;
        }
    }
}

// ---------------- attention scores f1/f2 (layer1) ----------------
__global__ __launch_bounds__(128) void f12_kernel(const float* __restrict__ a_heads) {
    int gw   = blockIdx.x * 4 + (threadIdx.x >> 5);
    int lane = threadIdx.x & 31;
    if (gw >= NH * NN) return;
    int h = gw / NN;
    const float* wh = g_Wh + (size_t)gw * HIDD;
    const float* a1 = a_heads + h * 2 * HIDD;
    float s1 = 0.f, s2 = 0.f;
    #pragma unroll
    for (int i = 0; i < 4; i++) {
        int o = lane + i * 32;
        float w = wh[o];
        s1 += w * a1[o];
        s2 += w * a1[HIDD + o];
    }
    #pragma unroll
    for (int off = 16; off; off >>= 1) {
        s1 += __shfl_down_sync(0xffffffffu, s1, off);
        s2 += __shfl_down_sync(0xffffffffu, s2, off);
    }
    if (lane == 0) { g_f1[gw] = s1; g_f2[gw] = s2; }
}

__global__ __launch_bounds__(128) void g12_kernel(const float* __restrict__ a_out) {
    int gw   = blockIdx.x * 4 + (threadIdx.x >> 5);
    int lane = threadIdx.x & 31;
    if (gw >= NN) return;
    const float* wh = g_Wh2 + (size_t)gw * HIDD;
    float s1 = 0.f, s2 = 0.f;
    #pragma unroll
    for (int i = 0; i < 4; i++) {
        int o = lane + i * 32;
        float w = wh[o];
        s1 += w * a_out[o];
        s2 += w * a_out[HIDD + o];
    }
    #pragma unroll
    for (int off = 16; off; off >>= 1) {
        s1 += __shfl_down_sync(0xffffffffu, s1, off);
        s2 += __shfl_down_sync(0xffffffffu, s2, off);
    }
    if (lane == 0) { g_g1[gw] = s1; g_g2[gw] = s2; }
}

// ---------------- fused masked-softmax + sparse aggregation ----------------
// layer==0: per-(head,row), out -> g_hcat with ELU. layer==1: single head, out -> dout.
__global__ __launch_bounds__(128) void attn_agg_kernel(int layer, float* __restrict__ dout) {
    int n = blockIdx.x;
    int h = blockIdx.y;
    int t = threadIdx.x;  // channel 0..127

    const float *Wh, *f1a, *f2a;
    float* outp;
    int rowStride;
    if (layer == 0) {
        Wh  = g_Wh + (size_t)h * NN * HIDD;
        f1a = g_f1 + (size_t)h * NN;
        f2a = g_f2 + (size_t)h * NN;
        outp = g_hcat;
        rowStride = NH * HIDD;
    } else {
        Wh = g_Wh2; f1a = g_g1; f2a = g_g2;
        outp = dout; rowStride = HIDD;
    }

    float f1n = f1a[n];
    int beg = g_rowptr[n], end = g_rowptr[n + 1];

    __shared__ float w_sh[128];
    __shared__ int   c_sh[128];
    __shared__ float red[128];

    const float NEGBIG = -3.0e38f;
    float m = NEGBIG, s = 0.f, acc = 0.f;

    for (int base = beg; base < end; base += 128) {
        int j = base + t;
        float e = NEGBIG;
        int col = 0;
        if (j < end) {
            col = g_cols[j];
            float v = f1n + f2a[col];
            e = (v > 0.f) ? v : ALPHAK * v;
        }
        c_sh[t] = col;
        red[t] = e;
        __syncthreads();
        #pragma unroll
        for (int o = 64; o; o >>= 1) {
            if (t < o) red[t] = fmaxf(red[t], red[t + o]);
            __syncthreads();
        }
        float cm = red[0];
        float nm = fmaxf(m, cm);
        float w = (j < end) ? __expf(e - nm) : 0.f;
        w_sh[t] = w;
        __syncthreads();   // protects red[0] read + publishes w_sh
        red[t] = w;
        __syncthreads();
        #pragma unroll
        for (int o = 64; o; o >>= 1) {
            if (t < o) red[t] += red[t + o];
            __syncthreads();
        }
        float ws = red[0];
        float scale = __expf(m - nm);
        s = s * scale + ws;
        acc = acc * scale;
        m = nm;

        int len = min(128, end - base);
        const float* __restrict__ Whp = Wh;
        #pragma unroll 4
        for (int jj = 0; jj < len; jj++) {
            acc = fmaf(w_sh[jj], Whp[(size_t)c_sh[jj] * HIDD + t], acc);
        }
        __syncthreads();   // before shared reuse next iteration
    }

    float r = acc / s;
    if (layer == 0) r = (r > 0.f) ? r : expm1f(r);
    outp[(size_t)n * rowStride + h * HIDD + t] = r;
}

// ---------------- launch ----------------
extern "C" void kernel_launch(void* const* d_in, const int* in_sizes, int n_in,
                              void* d_out, int out_size) {
    const float* x       = (const float*)d_in[0];
    const float* adj     = (const float*)d_in[1];
    const float* W_heads = (const float*)d_in[2];
    const float* a_heads = (const float*)d_in[3];
    const float* W_out   = (const float*)d_in[4];
    const float* a_out   = (const float*)d_in[5];
    float* out = (float*)d_out;

    // CSR build
    count_kernel<<<1500, 128>>>(adj);
    scan_kernel<<<1, 1024>>>();
    fill_kernel<<<1500, 128>>>(adj);

    // Wh = x @ W_heads  (batched over 8 heads), K=300, BK=12 (300 = 25*12)
    {
        dim3 g((NN + 63) / 64, NH);
        sgemm_k<12><<<g, 128>>>(x, W_heads, NN, FIN, FIN, (long)FIN * HIDD, 0);
    }
    // f1/f2
    f12_kernel<<<(NH * NN + 3) / 4, 128>>>(a_heads);

    // layer-1 attention + aggregation + ELU -> g_hcat
    {
        dim3 g(NN, NH);
        attn_agg_kernel<<<g, 128>>>(0, out);
    }

    // Wh2 = hcat @ W_out, K=1024, BK=16
    {
        dim3 g((NN + 63) / 64, 1);
        sgemm_k<16><<<g, 128>>>(nullptr, W_out, NN, NH * HIDD, NH * HIDD, 0L, 1);
    }
    // g1/g2
    g12_kernel<<<(NN + 3) / 4, 128>>>(a_out);

    // layer-2 attention -> d_out
    {
        dim3 g(NN, 1);
        attn_agg_kernel<<<g, 128>>>(1, out);
    }
}

// round 2
// speedup vs baseline: 1.2309x; 1.2309x over previous
#include <cuda_runtime.h>
#include <cuda_fp16.h>

#define NN    6000
#define FIN   300
#define HIDD  128
#define NH    8
#define ALPHAK 0.2f
#define MAXNNZ 4000000
#define SCAN_CH 6          // ceil(6000/1024)
#define NW 188             // ceil(6000/32) words per adjacency row

// ---------------- device scratch (static, no allocations) ----------------
__device__ float    g_Wh[NH * NN * HIDD];        // fp32 [h][n][o]
__device__ __half2  g_Wh16[NH * NN * (HIDD/2)];  // fp16 copy for gather
__device__ float    g_f1[NH * NN];
__device__ float    g_f2[NH * NN];
__device__ float    g_f2max[NH];
__device__ float    g_hcat[NN * NH * HIDD];
__device__ float    g_Wh2part[4 * NN * HIDD];    // split-K partials
__device__ float    g_Wh2[NN * HIDD];
__device__ float    g_g1[NN];
__device__ float    g_g2[NN];
__device__ float    g_g2max[1];
__device__ int      g_rowptr[NN + 1];
__device__ unsigned g_bits[NN * NW];
__device__ int      g_cols[MAXNNZ];

// ---------------- CSR build (count pass also emits bitmask) ----------------
__global__ __launch_bounds__(128) void count_kernel(const float* __restrict__ adj) {
    int row  = blockIdx.x * 4 + (threadIdx.x >> 5);
    int lane = threadIdx.x & 31;
    if (row >= NN) return;
    const float* arow = adj + (size_t)row * NN;
    int cnt = 0;
    for (int w0 = 0; w0 < NW; w0++) {
        int col = w0 * 32 + lane;
        float v = (col < NN) ? arow[col] : 0.f;
        unsigned b = __ballot_sync(0xffffffffu, v > 0.f);
        if (lane == 0) {
            g_bits[row * NW + w0] = b;
            cnt += __popc(b);
        }
    }
    if (lane == 0) g_rowptr[row + 1] = cnt;
}

__global__ __launch_bounds__(1024) void scan_kernel() {
    __shared__ int part[1024];
    int t = threadIdx.x;
    int base = t * SCAN_CH;
    int loc[SCAN_CH];
    int s = 0;
    #pragma unroll
    for (int i = 0; i < SCAN_CH; i++) {
        int idx = base + i;
        int v = (idx < NN) ? g_rowptr[idx + 1] : 0;
        s += v;
        loc[i] = s;
    }
    part[t] = s;
    __syncthreads();
    for (int off = 1; off < 1024; off <<= 1) {
        int v = 0;
        if (t >= off) v = part[t - off];
        __syncthreads();
        if (t >= off) part[t] += v;
        __syncthreads();
    }
    int excl = (t == 0) ? 0 : part[t - 1];
    #pragma unroll
    for (int i = 0; i < SCAN_CH; i++) {
        int idx = base + i;
        if (idx < NN) g_rowptr[idx + 1] = excl + loc[i];
    }
    if (t == 0) g_rowptr[0] = 0;
}

__global__ __launch_bounds__(128) void fill_kernel() {
    int row  = blockIdx.x * 4 + (threadIdx.x >> 5);
    int lane = threadIdx.x & 31;
    if (row >= NN) return;
    int base = g_rowptr[row];
    for (int w0 = 0; w0 < NW; w0++) {
        unsigned bits = g_bits[row * NW + w0];   // broadcast load
        if (bits) {
            if ((bits >> lane) & 1u) {
                int pos = base + __popc(bits & ((1u << lane) - 1u));
                g_cols[pos] = w0 * 32 + lane;
            }
            base += __popc(bits);
        }
    }
}

// ---------------- SGEMM 128x128 tiles, 256 threads, pipelined ----------------
// MODE 0: C = A[M,FIN] @ W_heads[h]  -> g_Wh (+fp16 copy), blockIdx.y = head
// MODE 1: split-K: C_part = g_hcat[:, s*256:(s+1)*256] @ W_out[s*256:...,:] -> g_Wh2part[s]
template <int BK, int MODE>
__global__ __launch_bounds__(256) void sgemm256(const float* __restrict__ A,
                                                const float* __restrict__ B) {
    constexpr int NLD = (128 * BK) / 256;
    __shared__ float As[BK][132];
    __shared__ float Bs[BK][128];

    int tid = threadIdx.x;
    int tx = tid & 15;
    int ty = tid >> 4;
    int m0 = blockIdx.x * 128;

    const float* Ab;
    const float* Bb;
    int kBeg, kEnd, ldA;
    if (MODE == 0) {
        Ab = A; Bb = B + (size_t)blockIdx.y * FIN * HIDD;
        kBeg = 0; kEnd = FIN; ldA = FIN;
    } else {
        Ab = g_hcat; Bb = B + (size_t)blockIdx.y * 256 * HIDD;
        kBeg = blockIdx.y * 256; kEnd = kBeg + 256; ldA = NH * HIDD;
    }

    float acc[8][8];
    #pragma unroll
    for (int i = 0; i < 8; i++)
        #pragma unroll
        for (int j = 0; j < 8; j++) acc[i][j] = 0.f;

    float pa[NLD], pb[NLD];
    auto loadG = [&](int k0) {
        #pragma unroll
        for (int i = 0; i < NLD; i++) {
            int idx = tid + i * 256;
            int r = idx / BK, c = idx % BK;
            int gm = m0 + r;
            pa[i] = (gm < NN) ? Ab[(size_t)gm * ldA + k0 + c] : 0.f;
        }
        #pragma unroll
        for (int i = 0; i < NLD; i++) {
            int idx = tid + i * 256;
            int r = idx >> 7, c = idx & 127;
            pb[i] = Bb[(size_t)(k0 - kBeg + r) * 128 + c];
        }
    };

    loadG(kBeg);
    int nIt = (kEnd - kBeg) / BK;
    for (int it = 0; it < nIt; it++) {
        #pragma unroll
        for (int i = 0; i < NLD; i++) {
            int idx = tid + i * 256;
            As[idx % BK][idx / BK] = pa[i];
        }
        #pragma unroll
        for (int i = 0; i < NLD; i++) {
            int idx = tid + i * 256;
            Bs[idx >> 7][idx & 127] = pb[i];
        }
        __syncthreads();
        if (it + 1 < nIt) loadG(kBeg + (it + 1) * BK);
        #pragma unroll
        for (int kk = 0; kk < BK; kk++) {
            float a[8], b[8];
            float4 a0 = *reinterpret_cast<const float4*>(&As[kk][ty * 8]);
            float4 a1 = *reinterpret_cast<const float4*>(&As[kk][ty * 8 + 4]);
            float4 b0 = *reinterpret_cast<const float4*>(&Bs[kk][tx * 8]);
            float4 b1 = *reinterpret_cast<const float4*>(&Bs[kk][tx * 8 + 4]);
            a[0]=a0.x; a[1]=a0.y; a[2]=a0.z; a[3]=a0.w;
            a[4]=a1.x; a[5]=a1.y; a[6]=a1.z; a[7]=a1.w;
            b[0]=b0.x; b[1]=b0.y; b[2]=b0.z; b[3]=b0.w;
            b[4]=b1.x; b[5]=b1.y; b[6]=b1.z; b[7]=b1.w;
            #pragma unroll
            for (int i = 0; i < 8; i++)
                #pragma unroll
                for (int j = 0; j < 8; j++)
                    acc[i][j] = fmaf(a[i], b[j], acc[i][j]);
        }
        __syncthreads();
    }

    if (MODE == 0) {
        float*   C   = g_Wh   + (size_t)blockIdx.y * NN * HIDD;
        __half2* C16 = g_Wh16 + (size_t)blockIdx.y * NN * (HIDD/2);
        #pragma unroll
        for (int i = 0; i < 8; i++) {
            int gm = m0 + ty * 8 + i;
            if (gm < NN) {
                *reinterpret_cast<float4*>(&C[(size_t)gm * 128 + tx * 8])     =
                    make_float4(acc[i][0], acc[i][1], acc[i][2], acc[i][3]);
                *reinterpret_cast<float4*>(&C[(size_t)gm * 128 + tx * 8 + 4]) =
                    make_float4(acc[i][4], acc[i][5], acc[i][6], acc[i][7]);
                #pragma unroll
                for (int j = 0; j < 4; j++)
                    C16[(size_t)gm * 64 + tx * 4 + j] =
                        __float22half2_rn(make_float2(acc[i][2*j], acc[i][2*j+1]));
            }
        }
    } else {
        float* C = g_Wh2part + (size_t)blockIdx.y * NN * HIDD;
        #pragma unroll
        for (int i = 0; i < 8; i++) {
            int gm = m0 + ty * 8 + i;
            if (gm < NN) {
                *reinterpret_cast<float4*>(&C[(size_t)gm * 128 + tx * 8])     =
                    make_float4(acc[i][0], acc[i][1], acc[i][2], acc[i][3]);
                *reinterpret_cast<float4*>(&C[(size_t)gm * 128 + tx * 8 + 4]) =
                    make_float4(acc[i][4], acc[i][5], acc[i][6], acc[i][7]);
            }
        }
    }
}

// ---------------- attention scores f1/f2 ----------------
__global__ __launch_bounds__(128) void f12_kernel(const float* __restrict__ a_heads) {
    int gw   = blockIdx.x * 4 + (threadIdx.x >> 5);
    int lane = threadIdx.x & 31;
    if (gw >= NH * NN) return;
    int h = gw / NN;
    const float* wh = g_Wh + (size_t)gw * HIDD;
    const float* a1 = a_heads + h * 2 * HIDD;
    float s1 = 0.f, s2 = 0.f;
    #pragma unroll
    for (int i = 0; i < 4; i++) {
        int o = lane + i * 32;
        float w = wh[o];
        s1 += w * a1[o];
        s2 += w * a1[HIDD + o];
    }
    #pragma unroll
    for (int off = 16; off; off >>= 1) {
        s1 += __shfl_down_sync(0xffffffffu, s1, off);
        s2 += __shfl_down_sync(0xffffffffu, s2, off);
    }
    if (lane == 0) { g_f1[gw] = s1; g_f2[gw] = s2; }
}

__global__ __launch_bounds__(256) void f2max_kernel() {
    __shared__ float red[256];
    int h = blockIdx.x, t = threadIdx.x;
    float m = -3.0e38f;
    for (int i = t; i < NN; i += 256) m = fmaxf(m, g_f2[(size_t)h * NN + i]);
    red[t] = m;
    __syncthreads();
    for (int o = 128; o; o >>= 1) {
        if (t < o) red[t] = fmaxf(red[t], red[t + o]);
        __syncthreads();
    }
    if (t == 0) g_f2max[h] = red[0];
}

__global__ __launch_bounds__(1024) void g2max_kernel() {
    __shared__ float red[1024];
    int t = threadIdx.x;
    float m = -3.0e38f;
    for (int i = t; i < NN; i += 1024) m = fmaxf(m, g_g2[i]);
    red[t] = m;
    __syncthreads();
    for (int o = 512; o; o >>= 1) {
        if (t < o) red[t] = fmaxf(red[t], red[t + o]);
        __syncthreads();
    }
    if (t == 0) g_g2max[0] = red[0];
}

// ---------------- layer-1: shifted-softmax + fp16 sparse aggregation + ELU ----------------
__global__ __launch_bounds__(128) void attn1_kernel() {
    int n = blockIdx.x, h = blockIdx.y, t = threadIdx.x;
    int c2 = t & 63, grp = t >> 6;
    const __half2* __restrict__ W   = g_Wh16 + (size_t)h * NN * 64;
    const float*   __restrict__ f2a = g_f2  + (size_t)h * NN;
    float f1n   = g_f1[(size_t)h * NN + n];
    float shift = f1n + g_f2max[h];
    int beg = g_rowptr[n], end = g_rowptr[n + 1];

    __shared__ float w_sh[128];
    __shared__ int   c_sh[128];
    __shared__ float red[128];
    __shared__ float2 cbuf[64];

    float2 acc = make_float2(0.f, 0.f);
    float s = 0.f;

    for (int base = beg; base < end; base += 128) {
        int len = end - base;
        if (len > 128) len = 128;
        float w = 0.f;
        if (t < len) {
            int col = g_cols[base + t];
            c_sh[t] = col;
            float v = f1n + f2a[col];
            v = (v > 0.f) ? v : ALPHAK * v;
            w = __expf(v - shift);
        }
        w_sh[t] = w;
        s += w;
        __syncthreads();
        #pragma unroll 4
        for (int jj = grp; jj < len; jj += 2) {
            float ww = w_sh[jj];
            float2 f = __half22float2(W[(size_t)c_sh[jj] * 64 + c2]);
            acc.x = fmaf(ww, f.x, acc.x);
            acc.y = fmaf(ww, f.y, acc.y);
        }
        __syncthreads();
    }

    red[t] = s;
    if (grp) cbuf[c2] = acc;
    __syncthreads();
    for (int o = 64; o; o >>= 1) {
        if (t < o) red[t] += red[t + o];
        __syncthreads();
    }
    if (!grp) {
        float inv = 1.f / red[0];
        float rx = (acc.x + cbuf[c2].x) * inv;
        float ry = (acc.y + cbuf[c2].y) * inv;
        rx = (rx > 0.f) ? rx : expm1f(rx);
        ry = (ry > 0.f) ? ry : expm1f(ry);
        float2* op = reinterpret_cast<float2*>(g_hcat + (size_t)n * NH * HIDD + h * HIDD);
        op[c2] = make_float2(rx, ry);
    }
}

// ---------------- split-K reduce + g1/g2 ----------------
__global__ __launch_bounds__(128) void reduce_g12_kernel(const float* __restrict__ a_out) {
    int n = blockIdx.x, t = threadIdx.x;
    size_t idx = (size_t)n * 128 + t;
    float w = g_Wh2part[idx]
            + g_Wh2part[(size_t)NN * 128 + idx]
            + g_Wh2part[(size_t)2 * NN * 128 + idx]
            + g_Wh2part[(size_t)3 * NN * 128 + idx];
    g_Wh2[idx] = w;
    __shared__ float r1[128], r2[128];
    r1[t] = w * a_out[t];
    r2[t] = w * a_out[128 + t];
    __syncthreads();
    for (int o = 64; o; o >>= 1) {
        if (t < o) { r1[t] += r1[t + o]; r2[t] += r2[t + o]; }
        __syncthreads();
    }
    if (t == 0) { g_g1[n] = r1[0]; g_g2[n] = r2[0]; }
}

// ---------------- layer-2: shifted-softmax + fp32 sparse aggregation ----------------
__global__ __launch_bounds__(128) void attn2_kernel(float* __restrict__ dout) {
    int n = blockIdx.x, t = threadIdx.x;
    int c2 = t & 63, grp = t >> 6;
    const float2* __restrict__ W = reinterpret_cast<const float2*>(g_Wh2);
    float g1n   = g_g1[n];
    float shift = g1n + g_g2max[0];
    int beg = g_rowptr[n], end = g_rowptr[n + 1];

    __shared__ float w_sh[128];
    __shared__ int   c_sh[128];
    __shared__ float red[128];
    __shared__ float2 cbuf[64];

    float2 acc = make_float2(0.f, 0.f);
    float s = 0.f;

    for (int base = beg; base < end; base += 128) {
        int len = end - base;
        if (len > 128) len = 128;
        float w = 0.f;
        if (t < len) {
            int col = g_cols[base + t];
            c_sh[t] = col;
            float v = g1n + g_g2[col];
            v = (v > 0.f) ? v : ALPHAK * v;
            w = __expf(v - shift);
        }
        w_sh[t] = w;
        s += w;
        __syncthreads();
        #pragma unroll 4
        for (int jj = grp; jj < len; jj += 2) {
            float ww = w_sh[jj];
            float2 f = W[(size_t)c_sh[jj] * 64 + c2];
            acc.x = fmaf(ww, f.x, acc.x);
            acc.y = fmaf(ww, f.y, acc.y);
        }
        __syncthreads();
    }

    red[t] = s;
    if (grp) cbuf[c2] = acc;
    __syncthreads();
    for (int o = 64; o; o >>= 1) {
        if (t < o) red[t] += red[t + o];
        __syncthreads();
    }
    if (!grp) {
        float inv = 1.f / red[0];
        float2* op = reinterpret_cast<float2*>(dout + (size_t)n * HIDD);
        op[c2] = make_float2((acc.x + cbuf[c2].x) * inv, (acc.y + cbuf[c2].y) * inv);
    }
}

// ---------------- launch ----------------
extern "C" void kernel_launch(void* const* d_in, const int* in_sizes, int n_in,
                              void* d_out, int out_size) {
    const float* x       = (const float*)d_in[0];
    const float* adj     = (const float*)d_in[1];
    const float* W_heads = (const float*)d_in[2];
    const float* a_heads = (const float*)d_in[3];
    const float* W_out   = (const float*)d_in[4];
    const float* a_out   = (const float*)d_in[5];
    float* out = (float*)d_out;

    count_kernel<<<1500, 128>>>(adj);
    scan_kernel<<<1, 1024>>>();
    fill_kernel<<<1500, 128>>>();

    sgemm256<12, 0><<<dim3(47, 8), 256>>>(x, W_heads);
    f12_kernel<<<(NH * NN + 3) / 4, 128>>>(a_heads);
    f2max_kernel<<<NH, 256>>>();

    attn1_kernel<<<dim3(NN, NH), 128>>>();

    sgemm256<16, 1><<<dim3(47, 4), 256>>>(nullptr, W_out);
    reduce_g12_kernel<<<NN, 128>>>(a_out);
    g2max_kernel<<<1, 1024>>>();

    attn2_kernel<<<NN, 128>>>(out);
}

// round 3
// speedup vs baseline: 2.0042x; 1.6282x over previous
#include <cuda_runtime.h>
#include <cuda_fp16.h>
#include <cstdint>

#define NN    6000
#define FIN   300
#define HIDD  128
#define NH    8
#define ALPHAK 0.2f
#define MAXNNZ 4000000
#define SCAN_CH 6          // ceil(6000/1024)
#define NW 188             // ceil(6000/32)

// ---------------- device scratch ----------------
__device__ __align__(256) __half g_Wh16[NN * NH * HIDD];   // [n][h][c] fp16, 12 MB
__device__ float    g_f1c[NN * NH];                        // [n][h]
__device__ float    g_f2c[NN * NH];                        // [n][h]
__device__ float    g_f2max[NH];
__device__ __align__(256) __half g_hcat16[NN * NH * HIDD]; // [n][h*128+c] fp16
__device__ float    g_Wh2part[4 * NN * HIDD];              // split-K fp32 partials
__device__ __align__(256) __half g_Wh2h[NN * HIDD];        // fp16 Wh2 for gather
__device__ float    g_g1[NN];
__device__ float    g_g2[NN];
__device__ float    g_g2max[1];
__device__ int      g_rowptr[NN + 1];
__device__ unsigned g_bits[NN * NW];
__device__ int      g_cols[MAXNNZ];

// ---------------- CSR build ----------------
__global__ __launch_bounds__(128) void count_kernel(const float* __restrict__ adj) {
    int row  = blockIdx.x * 4 + (threadIdx.x >> 5);
    int lane = threadIdx.x & 31;
    if (row >= NN) return;
    const float* arow = adj + (size_t)row * NN;
    int cnt = 0;
    for (int w0 = 0; w0 < NW; w0++) {
        int col = w0 * 32 + lane;
        float v = (col < NN) ? arow[col] : 0.f;
        unsigned b = __ballot_sync(0xffffffffu, v > 0.f);
        if (lane == 0) {
            g_bits[row * NW + w0] = b;
            cnt += __popc(b);
        }
    }
    if (lane == 0) g_rowptr[row + 1] = cnt;
}

__global__ __launch_bounds__(1024) void scan_kernel() {
    __shared__ int part[1024];
    int t = threadIdx.x;
    int base = t * SCAN_CH;
    int loc[SCAN_CH];
    int s = 0;
    #pragma unroll
    for (int i = 0; i < SCAN_CH; i++) {
        int idx = base + i;
        int v = (idx < NN) ? g_rowptr[idx + 1] : 0;
        s += v;
        loc[i] = s;
    }
    part[t] = s;
    __syncthreads();
    for (int off = 1; off < 1024; off <<= 1) {
        int v = 0;
        if (t >= off) v = part[t - off];
        __syncthreads();
        if (t >= off) part[t] += v;
        __syncthreads();
    }
    int excl = (t == 0) ? 0 : part[t - 1];
    #pragma unroll
    for (int i = 0; i < SCAN_CH; i++) {
        int idx = base + i;
        if (idx < NN) g_rowptr[idx + 1] = excl + loc[i];
    }
    if (t == 0) g_rowptr[0] = 0;
}

__global__ __launch_bounds__(128) void fill_kernel() {
    int row  = blockIdx.x * 4 + (threadIdx.x >> 5);
    int lane = threadIdx.x & 31;
    if (row >= NN) return;
    int base = g_rowptr[row];
    for (int w0 = 0; w0 < NW; w0++) {
        unsigned bits = g_bits[row * NW + w0];
        if (bits) {
            if ((bits >> lane) & 1u) {
                int pos = base + __popc(bits & ((1u << lane) - 1u));
                g_cols[pos] = w0 * 32 + lane;
            }
            base += __popc(bits);
        }
    }
}

// ---------------- tensor-core fp16 GEMM ----------------
__device__ __forceinline__ void mma16816(float* c, const uint32_t* a, const uint32_t* b) {
    asm volatile(
        "mma.sync.aligned.m16n8k16.row.col.f32.f16.f16.f32 "
        "{%0,%1,%2,%3}, {%4,%5,%6,%7}, {%8,%9}, {%0,%1,%2,%3};\n"
        : "+f"(c[0]), "+f"(c[1]), "+f"(c[2]), "+f"(c[3])
        : "r"(a[0]), "r"(a[1]), "r"(a[2]), "r"(a[3]), "r"(b[0]), "r"(b[1]));
}

// MODE 0: C[m, h*128+c] = x[m,300] @ W_heads[h]  -> g_Wh16 (fp16), grid (47, 8)
// MODE 1: partial[s] = hcat16[:, s*256:(s+1)*256] @ W_out[s*256:,:] -> g_Wh2part fp32, grid (47,4)
template <int MODE>
__global__ __launch_bounds__(256) void hgemm(const float* __restrict__ Af,
                                             const float* __restrict__ Bf) {
    constexpr int KTOT = (MODE == 0) ? FIN : 256;
    constexpr int NIT  = (KTOT + 15) / 16;
    __shared__ __half As[128][18];
    __shared__ __half Bs[128][18];

    int tid  = threadIdx.x;
    int lane = tid & 31;
    int wid  = tid >> 5;
    int wm = wid & 3, wn = wid >> 2;
    int m0 = blockIdx.x * 128;
    int sl = blockIdx.y;
    const float* Bg = Bf + (size_t)sl * ((MODE == 0) ? FIN * HIDD : 256 * HIDD);

    float acc[2][8][4];
    #pragma unroll
    for (int i = 0; i < 2; i++)
        #pragma unroll
        for (int j = 0; j < 8; j++)
            #pragma unroll
            for (int q = 0; q < 4; q++) acc[i][j][q] = 0.f;

    float4 pa0, pa1, pb0, pb1;
    uint4  ph;
    const float4 Z4 = make_float4(0.f, 0.f, 0.f, 0.f);

    auto loadG = [&](int it) {
        int k0 = it * 16;
        if (MODE == 0) {
            int r0 = tid >> 2, coff = (tid & 3) * 4;
            bool kok = (k0 + coff) < FIN;
            int gr0 = m0 + r0, gr1 = gr0 + 64;
            pa0 = (kok && gr0 < NN) ? *(const float4*)(Af + (size_t)gr0 * FIN + k0 + coff) : Z4;
            pa1 = (kok && gr1 < NN) ? *(const float4*)(Af + (size_t)gr1 * FIN + k0 + coff) : Z4;
        } else {
            int r = tid >> 1, hoff = (tid & 1) * 8;
            int gr = m0 + r;
            ph = (gr < NN) ? *(const uint4*)(g_hcat16 + (size_t)gr * (NH * HIDD) + sl * 256 + k0 + hoff)
                           : make_uint4(0u, 0u, 0u, 0u);
        }
        int kr = tid >> 4, c0 = (tid & 15) * 8;
        bool kok2 = (MODE == 1) || ((k0 + kr) < FIN);
        pb0 = kok2 ? *(const float4*)(Bg + (size_t)(k0 + kr) * HIDD + c0)     : Z4;
        pb1 = kok2 ? *(const float4*)(Bg + (size_t)(k0 + kr) * HIDD + c0 + 4) : Z4;
    };

    auto stS = [&]() {
        if (MODE == 0) {
            int r0 = tid >> 2, coff = (tid & 3) * 4;
            *(__half2*)&As[r0][coff]          = __float22half2_rn(make_float2(pa0.x, pa0.y));
            *(__half2*)&As[r0][coff + 2]      = __float22half2_rn(make_float2(pa0.z, pa0.w));
            *(__half2*)&As[r0 + 64][coff]     = __float22half2_rn(make_float2(pa1.x, pa1.y));
            *(__half2*)&As[r0 + 64][coff + 2] = __float22half2_rn(make_float2(pa1.z, pa1.w));
        } else {
            int r = tid >> 1, hoff = (tid & 1) * 8;
            *(uint32_t*)&As[r][hoff]     = ph.x;
            *(uint32_t*)&As[r][hoff + 2] = ph.y;
            *(uint32_t*)&As[r][hoff + 4] = ph.z;
            *(uint32_t*)&As[r][hoff + 6] = ph.w;
        }
        int kr = tid >> 4, c0 = (tid & 15) * 8;
        Bs[c0 + 0][kr] = __float2half_rn(pb0.x);
        Bs[c0 + 1][kr] = __float2half_rn(pb0.y);
        Bs[c0 + 2][kr] = __float2half_rn(pb0.z);
        Bs[c0 + 3][kr] = __float2half_rn(pb0.w);
        Bs[c0 + 4][kr] = __float2half_rn(pb1.x);
        Bs[c0 + 5][kr] = __float2half_rn(pb1.y);
        Bs[c0 + 6][kr] = __float2half_rn(pb1.z);
        Bs[c0 + 7][kr] = __float2half_rn(pb1.w);
    };

    loadG(0);
    int r = lane >> 2, c2 = (lane & 3) * 2;
    for (int it = 0; it < NIT; it++) {
        stS();
        __syncthreads();
        if (it + 1 < NIT) loadG(it + 1);

        uint32_t afr[2][4], bfr[8][2];
        #pragma unroll
        for (int mi = 0; mi < 2; mi++) {
            int row = wm * 32 + mi * 16 + r;
            afr[mi][0] = *(const uint32_t*)&As[row][c2];
            afr[mi][1] = *(const uint32_t*)&As[row + 8][c2];
            afr[mi][2] = *(const uint32_t*)&As[row][c2 + 8];
            afr[mi][3] = *(const uint32_t*)&As[row + 8][c2 + 8];
        }
        #pragma unroll
        for (int ni = 0; ni < 8; ni++) {
            int col = wn * 64 + ni * 8 + r;
            bfr[ni][0] = *(const uint32_t*)&Bs[col][c2];
            bfr[ni][1] = *(const uint32_t*)&Bs[col][c2 + 8];
        }
        #pragma unroll
        for (int mi = 0; mi < 2; mi++)
            #pragma unroll
            for (int ni = 0; ni < 8; ni++)
                mma16816(acc[mi][ni], afr[mi], bfr[ni]);
        __syncthreads();
    }

    #pragma unroll
    for (int mi = 0; mi < 2; mi++)
        #pragma unroll
        for (int hh = 0; hh < 2; hh++) {
            int row = m0 + wm * 32 + mi * 16 + r + hh * 8;
            if (row < NN) {
                #pragma unroll
                for (int ni = 0; ni < 8; ni++) {
                    int col = wn * 64 + ni * 8 + c2;
                    if (MODE == 0) {
                        *(__half2*)(g_Wh16 + (size_t)row * 1024 + sl * 128 + col) =
                            __float22half2_rn(make_float2(acc[mi][ni][hh * 2], acc[mi][ni][hh * 2 + 1]));
                    } else {
                        *(float2*)(g_Wh2part + (size_t)sl * NN * HIDD + (size_t)row * HIDD + col) =
                            make_float2(acc[mi][ni][hh * 2], acc[mi][ni][hh * 2 + 1]);
                    }
                }
            }
        }
}

// ---------------- f1/f2 (fp16 Wh, fp32 dot) ----------------
__global__ __launch_bounds__(128) void f12_kernel(const float* __restrict__ a_heads) {
    int gw   = blockIdx.x * 4 + (threadIdx.x >> 5);   // gw = n*8 + h
    int lane = threadIdx.x & 31;
    if (gw >= NN * NH) return;
    int h = gw & 7;
    const __half2* wh = (const __half2*)(g_Wh16 + (size_t)gw * HIDD);
    const float* a1 = a_heads + h * 2 * HIDD;
    float s1 = 0.f, s2 = 0.f;
    #pragma unroll
    for (int i = 0; i < 2; i++) {
        int o2 = lane + i * 32;
        float2 w = __half22float2(wh[o2]);
        s1 += w.x * a1[2 * o2] + w.y * a1[2 * o2 + 1];
        s2 += w.x * a1[HIDD + 2 * o2] + w.y * a1[HIDD + 2 * o2 + 1];
    }
    #pragma unroll
    for (int off = 16; off; off >>= 1) {
        s1 += __shfl_down_sync(0xffffffffu, s1, off);
        s2 += __shfl_down_sync(0xffffffffu, s2, off);
    }
    if (lane == 0) { g_f1c[gw] = s1; g_f2c[gw] = s2; }
}

__global__ __launch_bounds__(256) void f2max_kernel() {
    __shared__ float red[256];
    int h = blockIdx.x, t = threadIdx.x;
    float m = -3.0e38f;
    for (int i = t; i < NN; i += 256) m = fmaxf(m, g_f2c[i * 8 + h]);
    red[t] = m;
    __syncthreads();
    for (int o = 128; o; o >>= 1) {
        if (t < o) red[t] = fmaxf(red[t], red[t + o]);
        __syncthreads();
    }
    if (t == 0) g_f2max[h] = red[0];
}

__global__ __launch_bounds__(1024) void g2max_kernel() {
    __shared__ float red[1024];
    int t = threadIdx.x;
    float m = -3.0e38f;
    for (int i = t; i < NN; i += 1024) m = fmaxf(m, g_g2[i]);
    red[t] = m;
    __syncthreads();
    for (int o = 512; o; o >>= 1) {
        if (t < o) red[t] = fmaxf(red[t], red[t + o]);
        __syncthreads();
    }
    if (t == 0) g_g2max[0] = red[0];
}

// ---------------- layer-1: all heads per node, contiguous 2KB gather ----------------
__global__ __launch_bounds__(256) void attn1_kernel() {
    int n = blockIdx.x;
    int t = threadIdx.x, w = t >> 5, lane = t & 31;
    float f1n   = g_f1c[n * 8 + w];
    float shift = f1n + g_f2max[w];
    int beg = g_rowptr[n], end = g_rowptr[n + 1];

    __shared__ int   c_sh[128];
    __shared__ float w_sh[8][128];

    float a0 = 0.f, a1 = 0.f, a2 = 0.f, a3 = 0.f;
    float s = 0.f;
    const __half* Wb = g_Wh16 + w * 128 + lane * 4;

    for (int base = beg; base < end; base += 128) {
        int len = end - base;
        if (len > 128) len = 128;
        __syncthreads();
        if (t < len) c_sh[t] = g_cols[base + t];
        __syncthreads();
        #pragma unroll
        for (int e = lane; e < 128; e += 32) {
            float wt = 0.f;
            if (e < len) {
                int col = c_sh[e];
                float v = f1n + g_f2c[col * 8 + w];
                v = (v > 0.f) ? v : ALPHAK * v;
                wt = __expf(v - shift);
            }
            w_sh[w][e] = wt;
            s += wt;
        }
        __syncwarp();
        #pragma unroll 4
        for (int jj = 0; jj < len; jj++) {
            int col  = c_sh[jj];
            float wt = w_sh[w][jj];
            uint2 d = *(const uint2*)(Wb + (size_t)col * 1024);
            float2 p0 = __half22float2(*(__half2*)&d.x);
            float2 p1 = __half22float2(*(__half2*)&d.y);
            a0 = fmaf(wt, p0.x, a0);
            a1 = fmaf(wt, p0.y, a1);
            a2 = fmaf(wt, p1.x, a2);
            a3 = fmaf(wt, p1.y, a3);
        }
    }
    #pragma unroll
    for (int o = 16; o; o >>= 1) s += __shfl_xor_sync(0xffffffffu, s, o);
    float inv = 1.f / s;
    a0 *= inv; a1 *= inv; a2 *= inv; a3 *= inv;
    a0 = (a0 > 0.f) ? a0 : expm1f(a0);
    a1 = (a1 > 0.f) ? a1 : expm1f(a1);
    a2 = (a2 > 0.f) ? a2 : expm1f(a2);
    a3 = (a3 > 0.f) ? a3 : expm1f(a3);
    __half2 h0 = __float22half2_rn(make_float2(a0, a1));
    __half2 h1 = __float22half2_rn(make_float2(a2, a3));
    uint2 o2;
    o2.x = *reinterpret_cast<uint32_t*>(&h0);
    o2.y = *reinterpret_cast<uint32_t*>(&h1);
    *(uint2*)(g_hcat16 + (size_t)n * 1024 + w * 128 + lane * 4) = o2;
}

// ---------------- split-K reduce + g1/g2 + fp16 Wh2 ----------------
__global__ __launch_bounds__(128) void reduce_g12_kernel(const float* __restrict__ a_out) {
    int n = blockIdx.x, t = threadIdx.x;
    size_t idx = (size_t)n * HIDD + t;
    float w = g_Wh2part[idx]
            + g_Wh2part[(size_t)NN * HIDD + idx]
            + g_Wh2part[(size_t)2 * NN * HIDD + idx]
            + g_Wh2part[(size_t)3 * NN * HIDD + idx];
    g_Wh2h[idx] = __float2half_rn(w);
    __shared__ float r1[128], r2[128];
    r1[t] = w * a_out[t];
    r2[t] = w * a_out[HIDD + t];
    __syncthreads();
    for (int o = 64; o; o >>= 1) {
        if (t < o) { r1[t] += r1[t + o]; r2[t] += r2[t + o]; }
        __syncthreads();
    }
    if (t == 0) { g_g1[n] = r1[0]; g_g2[n] = r2[0]; }
}

// ---------------- layer-2: fp16 gather ----------------
__global__ __launch_bounds__(128) void attn2_kernel(float* __restrict__ dout) {
    int n = blockIdx.x, t = threadIdx.x;
    int c2 = t & 63, grp = t >> 6;
    float g1n   = g_g1[n];
    float shift = g1n + g_g2max[0];
    int beg = g_rowptr[n], end = g_rowptr[n + 1];

    __shared__ float w_sh[128];
    __shared__ int   c_sh[128];
    __shared__ float red[128];
    __shared__ float2 cbuf[64];
    const __half2* __restrict__ W = (const __half2*)g_Wh2h;

    float2 acc = make_float2(0.f, 0.f);
    float s = 0.f;

    for (int base = beg; base < end; base += 128) {
        int len = end - base;
        if (len > 128) len = 128;
        float wgt = 0.f;
        if (t < len) {
            int col = g_cols[base + t];
            c_sh[t] = col;
            float v = g1n + g_g2[col];
            v = (v > 0.f) ? v : ALPHAK * v;
            wgt = __expf(v - shift);
        }
        w_sh[t] = wgt;
        s += wgt;
        __syncthreads();
        #pragma unroll 4
        for (int jj = grp; jj < len; jj += 2) {
            float ww = w_sh[jj];
            float2 f = __half22float2(W[(size_t)c_sh[jj] * 64 + c2]);
            acc.x = fmaf(ww, f.x, acc.x);
            acc.y = fmaf(ww, f.y, acc.y);
        }
        __syncthreads();
    }

    red[t] = s;
    if (grp) cbuf[c2] = acc;
    __syncthreads();
    for (int o = 64; o; o >>= 1) {
        if (t < o) red[t] += red[t + o];
        __syncthreads();
    }
    if (!grp) {
        float inv = 1.f / red[0];
        float2* op = reinterpret_cast<float2*>(dout + (size_t)n * HIDD);
        op[c2] = make_float2((acc.x + cbuf[c2].x) * inv, (acc.y + cbuf[c2].y) * inv);
    }
}

// ---------------- launch ----------------
extern "C" void kernel_launch(void* const* d_in, const int* in_sizes, int n_in,
                              void* d_out, int out_size) {
    const float* x       = (const float*)d_in[0];
    const float* adj     = (const float*)d_in[1];
    const float* W_heads = (const float*)d_in[2];
    const float* a_heads = (const float*)d_in[3];
    const float* W_out   = (const float*)d_in[4];
    const float* a_out   = (const float*)d_in[5];
    float* out = (float*)d_out;

    count_kernel<<<1500, 128>>>(adj);
    scan_kernel<<<1, 1024>>>();
    fill_kernel<<<1500, 128>>>();

    hgemm<0><<<dim3(47, 8), 256>>>(x, W_heads);
    f12_kernel<<<(NN * NH + 3) / 4, 128>>>(a_heads);
    f2max_kernel<<<NH, 256>>>();

    attn1_kernel<<<NN, 256>>>();

    hgemm<1><<<dim3(47, 4), 256>>>(nullptr, W_out);
    reduce_g12_kernel<<<NN, 128>>>(a_out);
    g2max_kernel<<<1, 1024>>>();

    attn2_kernel<<<NN, 128>>>(out);
}